// round 8
// baseline (speedup 1.0000x reference)
#include <cuda_runtime.h>
#include <math.h>
#include <stdint.h>

// ---------------- problem constants ----------------
#define BB    32
#define TT1   2048
#define TT2   512
#define NMEL  80
#define NATT  80
#define NTEXT 512
#define NSPK  512
#define TEMP  0.0005f

// ---------------- scratch (static device memory; no allocs) ----------------
__device__ float g_kspk[BB * NTEXT];
__device__ float g_qspk[BB * NMEL];
__device__ float g_kmid[BB * 1024 * TT2];
__device__ float g_kenc[BB * NATT * TT2];
__device__ float g_qmid1[BB * 160 * TT1];
__device__ float g_qmid2[BB * NMEL * TT1];
__device__ float g_qenc[BB * NATT * TT1];
__device__ float g_k2[BB * TT2];
__device__ float g_q2[BB * TT1];

// ---------------- helpers ---------------------------------------------------
__device__ __forceinline__ void mma_tf32(float d[4], const float a[4], const float b[2]) {
    asm volatile(
        "mma.sync.aligned.m16n8k8.row.col.f32.tf32.tf32.f32 "
        "{%0,%1,%2,%3}, {%4,%5,%6,%7}, {%8,%9}, {%0,%1,%2,%3};\n"
        : "+f"(d[0]), "+f"(d[1]), "+f"(d[2]), "+f"(d[3])
        : "r"(__float_as_uint(a[0])), "r"(__float_as_uint(a[1])),
          "r"(__float_as_uint(a[2])), "r"(__float_as_uint(a[3])),
          "r"(__float_as_uint(b[0])), "r"(__float_as_uint(b[1])));
}

// ---------------- speaker linear --------------------------------------------
__global__ void spkproj_kernel(const float* __restrict__ spk,
                               const float* __restrict__ W,
                               const float* __restrict__ bias,
                               float* __restrict__ out, int Cout) {
    int c = blockIdx.x, b = blockIdx.y, l = threadIdx.x;
    const float* s = spk + (size_t)b * NSPK;
    const float* w = W + (size_t)c * NSPK;
    float acc = 0.f;
    for (int i = l; i < NSPK; i += 32) acc += s[i] * w[i];
    #pragma unroll
    for (int o = 16; o > 0; o >>= 1) acc += __shfl_xor_sync(0xffffffffu, acc, o);
    if (l == 0) out[b * Cout + c] = acc + bias[c];
}

// ---------------- tf32 conv1d-as-GEMM v2 (double-buffered, dyn smem) --------
// Block tile 128(M) x 128(N), BK=32. 8 warps: 4(M) x 2(N), warp tile 32x64.
// Raw fp32 bits into mma.tf32 (hw truncation; accuracy margin ~200x).
// As[2][128][36] padded; Bs[2][32][128] swizzle col ^ (8*(k&3)).
#define CBM  128
#define CBN2 128
#define CBK  32
#define AKP  36
#define A_ELEMS (CBM * AKP)            // 4608 floats per stage
#define B_ELEMS (CBK * CBN2)           // 4096 floats per stage
#define CONV_SMEM_BYTES ((2 * (A_ELEMS + B_ELEMS)) * (int)sizeof(float))  // 69632

template <int KS, bool RELU>
__global__ __launch_bounds__(256)
void mma_convgemm2(const float* __restrict__ W, const float* __restrict__ bias,
                   const float* __restrict__ X, const float* __restrict__ addvec,
                   float* __restrict__ Y, int Cout, int Cin, int T) {
    extern __shared__ __align__(16) float dynsm[];
    // layout: As0 | As1 | Bs0 | Bs1
    float* Abase = dynsm;
    float* Bbase = dynsm + 2 * A_ELEMS;

    const int b = blockIdx.z;
    const int mBase = blockIdx.y * CBM;
    const int tBase = blockIdx.x * CBN2;
    const int KK = Cin * KS;
    const float* Xb = X + (size_t)b * Cin * T;
    const float* av = addvec ? addvec + (size_t)b * Cin : nullptr;

    const int tid  = threadIdx.x;
    const int lane = tid & 31;
    const int warp = tid >> 5;
    const int wm = (warp & 3) * 32;    // 4 warps in M
    const int wn = (warp >> 2) * 64;   // 2 warps in N
    const int gid = lane >> 2;         // 0..7
    const int tig = lane & 3;          // 0..3

    // A staging: row = tid>>1, k-offset = (tid&1)*16 (4x float4)
    const int arow  = tid >> 1;
    const int akoff = (tid & 1) * 16;
    // B staging: row k = tid>>3, col chunks (tid&7)*4 + 32*j (4x float4)
    const int bk   = tid >> 3;
    const int bn   = (tid & 7) * 4;
    const int bswz = (bk & 3) * 8;

    float4 aReg[4], bReg[4];

    auto loadA = [&](int kb) {
        const int grow = mBase + arow;
        const float* wrow = W + (size_t)grow * KK;
        #pragma unroll
        for (int v = 0; v < 4; ++v) {
            const int kk = kb + akoff + v * 4;
            float4 w4 = make_float4(0.f, 0.f, 0.f, 0.f);
            if (grow < Cout && kk < KK)          // KK mult of 16: chunk all-or-none
                w4 = *reinterpret_cast<const float4*>(&wrow[kk]);
            aReg[v] = w4;
        }
    };

    auto loadB = [&](int kb) {
        const int kk = kb + bk;
        const bool kval = kk < KK;
        int ci, d;
        if (KS == 1) { ci = kval ? kk : 0; d = 0; }
        else         { ci = kval ? kk / 3 : 0; d = kval ? kk - ci * 3 : 0; }
        const float* xr = Xb + (size_t)ci * T;
        const float addv = (KS == 3 && kval) ? av[ci] : 0.f;
        #pragma unroll
        for (int j = 0; j < 4; ++j) {
            float4 v = make_float4(0.f, 0.f, 0.f, 0.f);
            if (KS == 1) {
                if (kval) {
                    const int t0 = tBase + bn + 32 * j;          // aligned, in-bounds
                    v = *reinterpret_cast<const float4*>(&xr[t0]);
                }
            } else {
                const int t0 = tBase + bn + 32 * j + d - 1;
                if (kval) {
                    if (d == 1) {                                // aligned, in-bounds
                        v = *reinterpret_cast<const float4*>(&xr[t0]);
                        v.x += addv; v.y += addv; v.z += addv; v.w += addv;
                    } else {
                        float e[4];
                        #pragma unroll
                        for (int q = 0; q < 4; ++q) {
                            const int tt = t0 + q;
                            e[q] = (tt >= 0 && tt < T) ? (xr[tt] + addv) : 0.f;
                        }
                        v = make_float4(e[0], e[1], e[2], e[3]);
                    }
                }
            }
            bReg[j] = v;
        }
    };

    auto storeAB = [&](int s) {
        float* As = Abase + s * A_ELEMS;
        float* Bs = Bbase + s * B_ELEMS;
        #pragma unroll
        for (int v = 0; v < 4; ++v)
            *reinterpret_cast<float4*>(&As[arow * AKP + akoff + v * 4]) = aReg[v];
        #pragma unroll
        for (int j = 0; j < 4; ++j)
            *reinterpret_cast<float4*>(&Bs[bk * CBN2 + ((bn + 32 * j) ^ bswz)]) = bReg[j];
    };

    float acc[2][8][4];
    #pragma unroll
    for (int mi = 0; mi < 2; ++mi)
        #pragma unroll
        for (int ni = 0; ni < 8; ++ni)
            #pragma unroll
            for (int r = 0; r < 4; ++r) acc[mi][ni][r] = 0.f;

    const int nT = (KK + CBK - 1) / CBK;
    loadA(0); loadB(0); storeAB(0);
    __syncthreads();

    for (int t = 0; t < nT; ++t) {
        const int s = t & 1;
        const float* As = Abase + s * A_ELEMS;
        const float* Bs = Bbase + s * B_ELEMS;
        if (t + 1 < nT) { loadA((t + 1) * CBK); loadB((t + 1) * CBK); }

        #pragma unroll
        for (int s8 = 0; s8 < 4; ++s8) {
            const int k0 = s8 * 8;
            float a[2][4];
            #pragma unroll
            for (int mi = 0; mi < 2; ++mi) {
                const int r = wm + mi * 16 + gid;
                a[mi][0] = As[r * AKP + k0 + tig];
                a[mi][1] = As[(r + 8) * AKP + k0 + tig];
                a[mi][2] = As[r * AKP + k0 + tig + 4];
                a[mi][3] = As[(r + 8) * AKP + k0 + tig + 4];
            }
            const int fs = 8 * tig;
            #pragma unroll
            for (int ni = 0; ni < 8; ++ni) {
                float bf[2];
                const int n = wn + ni * 8 + gid;
                bf[0] = Bs[(k0 + tig) * CBN2 + (n ^ fs)];
                bf[1] = Bs[(k0 + tig + 4) * CBN2 + (n ^ fs)];
                mma_tf32(acc[0][ni], a[0], bf);
                mma_tf32(acc[1][ni], a[1], bf);
            }
        }

        if (t + 1 < nT) {
            __syncthreads();          // all reads of both buffers done
            storeAB(s ^ 1);
            __syncthreads();          // next buffer ready
        }
    }

    // ---- epilogue ----
    #pragma unroll
    for (int mi = 0; mi < 2; ++mi) {
        const int r0 = mBase + wm + mi * 16 + gid;
        const int r1 = r0 + 8;
        const float bv0 = (r0 < Cout) ? bias[r0] : 0.f;
        const float bv1 = (r1 < Cout) ? bias[r1] : 0.f;
        #pragma unroll
        for (int ni = 0; ni < 8; ++ni) {
            const int c = tBase + wn + ni * 8 + tig * 2;
            if (r0 < Cout) {
                float2 o;
                o.x = acc[mi][ni][0] + bv0;
                o.y = acc[mi][ni][1] + bv0;
                if (RELU) { o.x = fmaxf(o.x, 0.f); o.y = fmaxf(o.y, 0.f); }
                *reinterpret_cast<float2*>(&Y[((size_t)b * Cout + r0) * T + c]) = o;
            }
            if (r1 < Cout) {
                float2 o;
                o.x = acc[mi][ni][2] + bv1;
                o.y = acc[mi][ni][3] + bv1;
                if (RELU) { o.x = fmaxf(o.x, 0.f); o.y = fmaxf(o.y, 0.f); }
                *reinterpret_cast<float2*>(&Y[((size_t)b * Cout + r1) * T + c]) = o;
            }
        }
    }
}

// ---------------- channel-wise sum of squares -------------------------------
__global__ void sumsq_kernel(const float* __restrict__ X, float* __restrict__ out,
                             int C, int T) {
    int b = blockIdx.y;
    int t = blockIdx.x * blockDim.x + threadIdx.x;
    if (t >= T) return;
    const float* p = X + (size_t)b * C * T + t;
    float s = 0.f;
    for (int c = 0; c < C; ++c) {
        float v = p[(size_t)c * T];
        s = fmaf(v, v, s);
    }
    out[b * T + t] = s;
}

// ---------------- fused attention tail --------------------------------------
__global__ void attn_kernel(const float* __restrict__ qenc,
                            const float* __restrict__ kenc,
                            const float* __restrict__ q2,
                            const float* __restrict__ k2,
                            const float* __restrict__ prior,
                            const int* __restrict__ mask,
                            float* __restrict__ outA,
                            float* __restrict__ outLP) {
    extern __shared__ __align__(16) float sm[];
    float* ks_s = sm;                          // [80][512]
    float* qs   = ks_s + NATT * TT2;           // [80][32]
    float* k2s  = qs + NATT * 32;              // [512]
    float* q2s  = k2s + TT2;                   // [32]
    int*   ms   = (int*)(q2s + 32);            // [512]

    const int b = blockIdx.y;
    const int t1Base = blockIdx.x * 32;
    const int tid = threadIdx.x;

    {
        const float4* src = reinterpret_cast<const float4*>(kenc + (size_t)b * NATT * TT2);
        float4* dst = reinterpret_cast<float4*>(ks_s);
        for (int i = tid; i < NATT * TT2 / 4; i += 256) dst[i] = src[i];
        for (int i = tid; i < NATT * 32; i += 256) {
            int c = i / 32, r = i % 32;
            qs[i] = qenc[((size_t)b * NATT + c) * TT1 + t1Base + r];
        }
        for (int i = tid; i < TT2; i += 256) k2s[i] = k2[b * TT2 + i];
        if (tid < 32) q2s[tid] = q2[b * TT1 + t1Base + tid];
        for (int i = tid; i < TT2; i += 256) ms[i] = mask[b * TT2 + i];
    }
    __syncthreads();

    const int w = tid >> 5, l = tid & 31;
    const int r0 = w * 4;

    float acc[4][16];
    #pragma unroll
    for (int r = 0; r < 4; ++r)
        #pragma unroll
        for (int j = 0; j < 16; ++j) acc[r][j] = 0.f;

    for (int c = 0; c < NATT; ++c) {
        float4 q4 = *reinterpret_cast<const float4*>(&qs[c * 32 + r0]);
        float qv[4] = {q4.x, q4.y, q4.z, q4.w};
        #pragma unroll
        for (int g = 0; g < 4; ++g) {
            float4 kv = *reinterpret_cast<const float4*>(&ks_s[c * TT2 + g * 128 + l * 4]);
            #pragma unroll
            for (int r = 0; r < 4; ++r) {
                acc[r][g * 4 + 0] = fmaf(qv[r], kv.x, acc[r][g * 4 + 0]);
                acc[r][g * 4 + 1] = fmaf(qv[r], kv.y, acc[r][g * 4 + 1]);
                acc[r][g * 4 + 2] = fmaf(qv[r], kv.z, acc[r][g * 4 + 2]);
                acc[r][g * 4 + 3] = fmaf(qv[r], kv.w, acc[r][g * 4 + 3]);
            }
        }
    }

    float k2r[16];
    int mr[16];
    #pragma unroll
    for (int g = 0; g < 4; ++g) {
        float4 kk = *reinterpret_cast<const float4*>(&k2s[g * 128 + l * 4]);
        k2r[g * 4 + 0] = kk.x; k2r[g * 4 + 1] = kk.y;
        k2r[g * 4 + 2] = kk.z; k2r[g * 4 + 3] = kk.w;
        #pragma unroll
        for (int e = 0; e < 4; ++e) mr[g * 4 + e] = ms[g * 128 + l * 4 + e];
    }

    for (int r = 0; r < 4; ++r) {
        const int t1 = t1Base + r0 + r;
        const float q2v = q2s[r0 + r];

        float lg[16];
        float mx = -3.4e38f;
        #pragma unroll
        for (int j = 0; j < 16; ++j) {
            lg[j] = -TEMP * (q2v + k2r[j] - 2.f * acc[r][j]);
            mx = fmaxf(mx, lg[j]);
        }
        #pragma unroll
        for (int o = 16; o > 0; o >>= 1)
            mx = fmaxf(mx, __shfl_xor_sync(0xffffffffu, mx, o));

        float wv[16];
        float sum = 0.f;
        #pragma unroll
        for (int j = 0; j < 16; ++j) {
            lg[j] -= mx;
            wv[j] = __expf(lg[j]);
            sum += wv[j];
        }
        #pragma unroll
        for (int o = 16; o > 0; o >>= 1)
            sum += __shfl_xor_sync(0xffffffffu, sum, o);
        const float lsum = __logf(sum);

        const float* pr = prior + ((size_t)b * TT1 + t1) * TT2;
        float* olp = outLP + ((size_t)b * TT1 + t1) * TT2;
        #pragma unroll
        for (int g = 0; g < 4; ++g) {
            float4 p4 = *reinterpret_cast<const float4*>(&pr[g * 128 + l * 4]);
            float pa[4] = {p4.x + 1e-8f, p4.y + 1e-8f, p4.z + 1e-8f, p4.w + 1e-8f};
            float4 o;
            o.x = lg[g * 4 + 0] - lsum + __logf(pa[0]);
            o.y = lg[g * 4 + 1] - lsum + __logf(pa[1]);
            o.z = lg[g * 4 + 2] - lsum + __logf(pa[2]);
            o.w = lg[g * 4 + 3] - lsum + __logf(pa[3]);
            *reinterpret_cast<float4*>(&olp[g * 128 + l * 4]) = o;
            #pragma unroll
            for (int e = 0; e < 4; ++e) {
                int j = g * 4 + e;
                wv[j] = mr[j] ? 0.f : wv[j] * pa[e];
            }
        }

        float s2 = 0.f;
        #pragma unroll
        for (int j = 0; j < 16; ++j) s2 += wv[j];
        #pragma unroll
        for (int o = 16; o > 0; o >>= 1)
            s2 += __shfl_xor_sync(0xffffffffu, s2, o);
        const float inv = 1.f / s2;

        float* oa = outA + ((size_t)b * TT1 + t1) * TT2;
        #pragma unroll
        for (int g = 0; g < 4; ++g) {
            float4 o;
            o.x = wv[g * 4 + 0] * inv; o.y = wv[g * 4 + 1] * inv;
            o.z = wv[g * 4 + 2] * inv; o.w = wv[g * 4 + 3] * inv;
            *reinterpret_cast<float4*>(&oa[g * 128 + l * 4]) = o;
        }
    }
}

// ---------------- launch ----------------------------------------------------
extern "C" void kernel_launch(void* const* d_in, const int* in_sizes, int n_in,
                              void* d_out, int out_size) {
    const float* queries = (const float*)d_in[0];
    const float* keys    = (const float*)d_in[1];
    const int*   mask    = (const int*)d_in[2];
    const float* prior   = (const float*)d_in[3];
    const float* spk     = (const float*)d_in[4];
    const float* kw1 = (const float*)d_in[5];
    const float* kb1 = (const float*)d_in[6];
    const float* kw2 = (const float*)d_in[7];
    const float* kb2 = (const float*)d_in[8];
    const float* qw1 = (const float*)d_in[9];
    const float* qb1 = (const float*)d_in[10];
    const float* qw2 = (const float*)d_in[11];
    const float* qb2 = (const float*)d_in[12];
    const float* qw3 = (const float*)d_in[13];
    const float* qb3 = (const float*)d_in[14];
    const float* kspk_w = (const float*)d_in[15];
    const float* kspk_b = (const float*)d_in[16];
    const float* qspk_w = (const float*)d_in[17];
    const float* qspk_b = (const float*)d_in[18];

    float* outA  = (float*)d_out;
    float* outLP = (float*)d_out + (size_t)BB * TT1 * TT2;

    float *kspk, *qspk, *kmid, *kenc, *qmid1, *qmid2, *qenc, *k2, *q2;
    cudaGetSymbolAddress((void**)&kspk,  g_kspk);
    cudaGetSymbolAddress((void**)&qspk,  g_qspk);
    cudaGetSymbolAddress((void**)&kmid,  g_kmid);
    cudaGetSymbolAddress((void**)&kenc,  g_kenc);
    cudaGetSymbolAddress((void**)&qmid1, g_qmid1);
    cudaGetSymbolAddress((void**)&qmid2, g_qmid2);
    cudaGetSymbolAddress((void**)&qenc,  g_qenc);
    cudaGetSymbolAddress((void**)&k2,    g_k2);
    cudaGetSymbolAddress((void**)&q2,    g_q2);

    // dynamic smem attributes (set every call; deterministic, capture-safe)
    cudaFuncSetAttribute(mma_convgemm2<3, true>,
                         cudaFuncAttributeMaxDynamicSharedMemorySize, CONV_SMEM_BYTES);
    cudaFuncSetAttribute(mma_convgemm2<1, true>,
                         cudaFuncAttributeMaxDynamicSharedMemorySize, CONV_SMEM_BYTES);
    cudaFuncSetAttribute(mma_convgemm2<1, false>,
                         cudaFuncAttributeMaxDynamicSharedMemorySize, CONV_SMEM_BYTES);
    size_t smem = (size_t)(NATT * TT2 + NATT * 32 + TT2 + 32) * sizeof(float)
                + TT2 * sizeof(int);
    cudaFuncSetAttribute(attn_kernel, cudaFuncAttributeMaxDynamicSharedMemorySize,
                         (int)smem);

    // 1. speaker projections
    spkproj_kernel<<<dim3(NTEXT, BB), 32>>>(spk, kspk_w, kspk_b, kspk, NTEXT);
    spkproj_kernel<<<dim3(NMEL, BB), 32>>>(spk, qspk_w, qspk_b, qspk, NMEL);

    // 2. keys conv1 (512->1024, k3) + relu
    mma_convgemm2<3, true><<<dim3(TT2 / CBN2, 8, BB), 256, CONV_SMEM_BYTES>>>(
        kw1, kb1, keys, kspk, kmid, 1024, NTEXT, TT2);

    // 3. keys conv2 (1024->80, k1)
    mma_convgemm2<1, false><<<dim3(TT2 / CBN2, 1, BB), 256, CONV_SMEM_BYTES>>>(
        kw2, kb2, kmid, nullptr, kenc, NATT, 1024, TT2);

    // 4. queries conv1 (80->160, k3) + relu
    mma_convgemm2<3, true><<<dim3(TT1 / CBN2, 2, BB), 256, CONV_SMEM_BYTES>>>(
        qw1, qb1, queries, qspk, qmid1, 160, NMEL, TT1);

    // 5. queries conv2 (160->80, k1) + relu
    mma_convgemm2<1, true><<<dim3(TT1 / CBN2, 1, BB), 256, CONV_SMEM_BYTES>>>(
        qw2, qb2, qmid1, nullptr, qmid2, NMEL, 160, TT1);

    // 6. queries conv3 (80->80, k1)
    mma_convgemm2<1, false><<<dim3(TT1 / CBN2, 1, BB), 256, CONV_SMEM_BYTES>>>(
        qw3, qb3, qmid2, nullptr, qenc, NATT, NMEL, TT1);

    // 7. squared norms
    sumsq_kernel<<<dim3(TT2 / 256, BB), 256>>>(kenc, k2, NATT, TT2);
    sumsq_kernel<<<dim3(TT1 / 256, BB), 256>>>(qenc, q2, NATT, TT1);

    // 8. fused attention tail
    attn_kernel<<<dim3(TT1 / 32, BB), 256, smem>>>(
        qenc, kenc, q2, k2, prior, mask, outA, outLP);
}

// round 10
// speedup vs baseline: 1.4191x; 1.4191x over previous
#include <cuda_runtime.h>
#include <math.h>
#include <stdint.h>

// ---------------- problem constants ----------------
#define BB    32
#define TT1   2048
#define TT2   512
#define NMEL  80
#define NATT  80
#define NTEXT 512
#define NSPK  512
#define TEMP  0.0005f

// ---------------- scratch (static device memory; no allocs) ----------------
__device__ float g_kspk[BB * NTEXT];
__device__ float g_qspk[BB * NMEL];
__device__ float g_kmid[BB * 1024 * TT2];
__device__ float g_kenc[BB * NATT * TT2];
__device__ float g_qmid1[BB * 160 * TT1];
__device__ float g_qmid2[BB * NMEL * TT1];
__device__ float g_qenc[BB * NATT * TT1];
__device__ float g_k2[BB * TT2];
__device__ float g_q2[BB * TT1];

// ---------------- helpers ---------------------------------------------------
__device__ __forceinline__ void mma_tf32(float d[4], const float a[4], const float b[2]) {
    asm volatile(
        "mma.sync.aligned.m16n8k8.row.col.f32.tf32.tf32.f32 "
        "{%0,%1,%2,%3}, {%4,%5,%6,%7}, {%8,%9}, {%0,%1,%2,%3};\n"
        : "+f"(d[0]), "+f"(d[1]), "+f"(d[2]), "+f"(d[3])
        : "r"(__float_as_uint(a[0])), "r"(__float_as_uint(a[1])),
          "r"(__float_as_uint(a[2])), "r"(__float_as_uint(a[3])),
          "r"(__float_as_uint(b[0])), "r"(__float_as_uint(b[1])));
}

// ---------------- speaker linear --------------------------------------------
__global__ void spkproj_kernel(const float* __restrict__ spk,
                               const float* __restrict__ W,
                               const float* __restrict__ bias,
                               float* __restrict__ out, int Cout) {
    int c = blockIdx.x, b = blockIdx.y, l = threadIdx.x;
    const float* s = spk + (size_t)b * NSPK;
    const float* w = W + (size_t)c * NSPK;
    float acc = 0.f;
    for (int i = l; i < NSPK; i += 32) acc += s[i] * w[i];
    #pragma unroll
    for (int o = 16; o > 0; o >>= 1) acc += __shfl_xor_sync(0xffffffffu, acc, o);
    if (l == 0) out[b * Cout + c] = acc + bias[c];
}

// ---------------- tf32 conv1d-as-GEMM v3 ------------------------------------
// 128(M) x 64(N) block tile, BK=32, double-buffered register prefetch,
// ONE __syncthreads per K-iter, 2 CTAs/SM (__launch_bounds__(256,2)).
// As[2][128][36] padded; Bs[2][32][64] swizzle col ^ (8*(k&3)).
#define CBM  128
#define CBN  64
#define CBK  32
#define AKP  36
#define A_ELEMS (CBM * AKP)            // 4608
#define B_ELEMS (CBK * CBN)            // 2048
#define CONV_SMEM_BYTES ((2 * (A_ELEMS + B_ELEMS)) * (int)sizeof(float))  // 53248

template <int KS, bool RELU>
__global__ __launch_bounds__(256, 2)
void mma_convgemm3(const float* __restrict__ W, const float* __restrict__ bias,
                   const float* __restrict__ X, const float* __restrict__ addvec,
                   float* __restrict__ Y, int Cout, int Cin, int T) {
    extern __shared__ __align__(16) float dynsm[];
    float* Abase = dynsm;                       // As0 | As1 | Bs0 | Bs1
    float* Bbase = dynsm + 2 * A_ELEMS;

    const int b = blockIdx.z;
    const int mBase = blockIdx.y * CBM;
    const int tBase = blockIdx.x * CBN;
    const int KK = Cin * KS;
    const float* Xb = X + (size_t)b * Cin * T;
    const float* av = addvec ? addvec + (size_t)b * Cin : nullptr;

    const int tid  = threadIdx.x;
    const int lane = tid & 31;
    const int warp = tid >> 5;
    const int wm = (warp & 3) * 32;    // 4 warps in M
    const int wn = (warp >> 2) * 32;   // 2 warps in N
    const int gid = lane >> 2;         // 0..7
    const int tig = lane & 3;          // 0..3

    // A staging: row = tid>>1, k-offset = (tid&1)*16 (4x float4)
    const int arow  = tid >> 1;
    const int akoff = (tid & 1) * 16;
    // B staging: row k = tid>>3, col chunks (tid&7)*4 + 32*j, j<2 (2x float4)
    const int bk   = tid >> 3;
    const int bn   = (tid & 7) * 4;
    const int bswz = (bk & 3) * 8;

    float4 aReg[4], bReg[2];

    auto loadA = [&](int kb) {
        const int grow = mBase + arow;
        const float* wrow = W + (size_t)grow * KK;
        #pragma unroll
        for (int v = 0; v < 4; ++v) {
            const int kk = kb + akoff + v * 4;
            float4 w4 = make_float4(0.f, 0.f, 0.f, 0.f);
            if (grow < Cout && kk < KK)          // KK mult of 16: chunk all-or-none
                w4 = *reinterpret_cast<const float4*>(&wrow[kk]);
            aReg[v] = w4;
        }
    };

    auto loadB = [&](int kb) {
        const int kk = kb + bk;
        const bool kval = kk < KK;
        int ci, d;
        if (KS == 1) { ci = kval ? kk : 0; d = 0; }
        else         { ci = kval ? kk / 3 : 0; d = kval ? kk - ci * 3 : 0; }
        const float* xr = Xb + (size_t)ci * T;
        const float addv = (KS == 3 && kval) ? av[ci] : 0.f;
        #pragma unroll
        for (int j = 0; j < 2; ++j) {
            float4 v = make_float4(0.f, 0.f, 0.f, 0.f);
            if (KS == 1) {
                if (kval) {
                    const int t0 = tBase + bn + 32 * j;          // aligned, in-bounds
                    v = *reinterpret_cast<const float4*>(&xr[t0]);
                }
            } else {
                const int t0 = tBase + bn + 32 * j + d - 1;
                if (kval) {
                    if (d == 1) {                                // aligned, in-bounds
                        v = *reinterpret_cast<const float4*>(&xr[t0]);
                        v.x += addv; v.y += addv; v.z += addv; v.w += addv;
                    } else {
                        float e[4];
                        #pragma unroll
                        for (int q = 0; q < 4; ++q) {
                            const int tt = t0 + q;
                            e[q] = (tt >= 0 && tt < T) ? (xr[tt] + addv) : 0.f;
                        }
                        v = make_float4(e[0], e[1], e[2], e[3]);
                    }
                }
            }
            bReg[j] = v;
        }
    };

    auto storeAB = [&](int s) {
        float* As = Abase + s * A_ELEMS;
        float* Bs = Bbase + s * B_ELEMS;
        #pragma unroll
        for (int v = 0; v < 4; ++v)
            *reinterpret_cast<float4*>(&As[arow * AKP + akoff + v * 4]) = aReg[v];
        #pragma unroll
        for (int j = 0; j < 2; ++j)
            *reinterpret_cast<float4*>(&Bs[bk * CBN + ((bn + 32 * j) ^ bswz)]) = bReg[j];
    };

    float acc[2][4][4];
    #pragma unroll
    for (int mi = 0; mi < 2; ++mi)
        #pragma unroll
        for (int ni = 0; ni < 4; ++ni)
            #pragma unroll
            for (int r = 0; r < 4; ++r) acc[mi][ni][r] = 0.f;

    const int nT = (KK + CBK - 1) / CBK;
    loadA(0); loadB(0); storeAB(0);
    __syncthreads();

    for (int t = 0; t < nT; ++t) {
        const int s = t & 1;
        const float* As = Abase + s * A_ELEMS;
        const float* Bs = Bbase + s * B_ELEMS;
        if (t + 1 < nT) { loadA((t + 1) * CBK); loadB((t + 1) * CBK); }

        #pragma unroll
        for (int s8 = 0; s8 < 4; ++s8) {
            const int k0 = s8 * 8;
            float a[2][4];
            #pragma unroll
            for (int mi = 0; mi < 2; ++mi) {
                const int r = wm + mi * 16 + gid;
                a[mi][0] = As[r * AKP + k0 + tig];
                a[mi][1] = As[(r + 8) * AKP + k0 + tig];
                a[mi][2] = As[r * AKP + k0 + tig + 4];
                a[mi][3] = As[(r + 8) * AKP + k0 + tig + 4];
            }
            const int fs = 8 * tig;
            #pragma unroll
            for (int ni = 0; ni < 4; ++ni) {
                float bf[2];
                const int n = wn + ni * 8 + gid;
                bf[0] = Bs[(k0 + tig) * CBN + (n ^ fs)];
                bf[1] = Bs[(k0 + tig + 4) * CBN + (n ^ fs)];
                mma_tf32(acc[0][ni], a[0], bf);
                mma_tf32(acc[1][ni], a[1], bf);
            }
        }

        if (t + 1 < nT) {
            // Writes go to buffer s^1, last READ in iter t-1 (sealed by the
            // sync below in that iter). Concurrent readers here touch only s.
            storeAB(s ^ 1);
            __syncthreads();
        }
    }

    // ---- epilogue ----
    #pragma unroll
    for (int mi = 0; mi < 2; ++mi) {
        const int r0 = mBase + wm + mi * 16 + gid;
        const int r1 = r0 + 8;
        const float bv0 = (r0 < Cout) ? bias[r0] : 0.f;
        const float bv1 = (r1 < Cout) ? bias[r1] : 0.f;
        #pragma unroll
        for (int ni = 0; ni < 4; ++ni) {
            const int c = tBase + wn + ni * 8 + tig * 2;
            if (r0 < Cout) {
                float2 o;
                o.x = acc[mi][ni][0] + bv0;
                o.y = acc[mi][ni][1] + bv0;
                if (RELU) { o.x = fmaxf(o.x, 0.f); o.y = fmaxf(o.y, 0.f); }
                *reinterpret_cast<float2*>(&Y[((size_t)b * Cout + r0) * T + c]) = o;
            }
            if (r1 < Cout) {
                float2 o;
                o.x = acc[mi][ni][2] + bv1;
                o.y = acc[mi][ni][3] + bv1;
                if (RELU) { o.x = fmaxf(o.x, 0.f); o.y = fmaxf(o.y, 0.f); }
                *reinterpret_cast<float2*>(&Y[((size_t)b * Cout + r1) * T + c]) = o;
            }
        }
    }
}

// ---------------- channel-wise sum of squares -------------------------------
__global__ void sumsq_kernel(const float* __restrict__ X, float* __restrict__ out,
                             int C, int T) {
    int b = blockIdx.y;
    int t = blockIdx.x * blockDim.x + threadIdx.x;
    if (t >= T) return;
    const float* p = X + (size_t)b * C * T + t;
    float s = 0.f;
    for (int c = 0; c < C; ++c) {
        float v = p[(size_t)c * T];
        s = fmaf(v, v, s);
    }
    out[b * T + t] = s;
}

// ---------------- fused attention tail --------------------------------------
__global__ void attn_kernel(const float* __restrict__ qenc,
                            const float* __restrict__ kenc,
                            const float* __restrict__ q2,
                            const float* __restrict__ k2,
                            const float* __restrict__ prior,
                            const int* __restrict__ mask,
                            float* __restrict__ outA,
                            float* __restrict__ outLP) {
    extern __shared__ __align__(16) float sm[];
    float* ks_s = sm;                          // [80][512]
    float* qs   = ks_s + NATT * TT2;           // [80][32]
    float* k2s  = qs + NATT * 32;              // [512]
    float* q2s  = k2s + TT2;                   // [32]
    int*   ms   = (int*)(q2s + 32);            // [512]

    const int b = blockIdx.y;
    const int t1Base = blockIdx.x * 32;
    const int tid = threadIdx.x;

    {
        const float4* src = reinterpret_cast<const float4*>(kenc + (size_t)b * NATT * TT2);
        float4* dst = reinterpret_cast<float4*>(ks_s);
        for (int i = tid; i < NATT * TT2 / 4; i += 256) dst[i] = src[i];
        for (int i = tid; i < NATT * 32; i += 256) {
            int c = i / 32, r = i % 32;
            qs[i] = qenc[((size_t)b * NATT + c) * TT1 + t1Base + r];
        }
        for (int i = tid; i < TT2; i += 256) k2s[i] = k2[b * TT2 + i];
        if (tid < 32) q2s[tid] = q2[b * TT1 + t1Base + tid];
        for (int i = tid; i < TT2; i += 256) ms[i] = mask[b * TT2 + i];
    }
    __syncthreads();

    const int w = tid >> 5, l = tid & 31;
    const int r0 = w * 4;

    float acc[4][16];
    #pragma unroll
    for (int r = 0; r < 4; ++r)
        #pragma unroll
        for (int j = 0; j < 16; ++j) acc[r][j] = 0.f;

    for (int c = 0; c < NATT; ++c) {
        float4 q4 = *reinterpret_cast<const float4*>(&qs[c * 32 + r0]);
        float qv[4] = {q4.x, q4.y, q4.z, q4.w};
        #pragma unroll
        for (int g = 0; g < 4; ++g) {
            float4 kv = *reinterpret_cast<const float4*>(&ks_s[c * TT2 + g * 128 + l * 4]);
            #pragma unroll
            for (int r = 0; r < 4; ++r) {
                acc[r][g * 4 + 0] = fmaf(qv[r], kv.x, acc[r][g * 4 + 0]);
                acc[r][g * 4 + 1] = fmaf(qv[r], kv.y, acc[r][g * 4 + 1]);
                acc[r][g * 4 + 2] = fmaf(qv[r], kv.z, acc[r][g * 4 + 2]);
                acc[r][g * 4 + 3] = fmaf(qv[r], kv.w, acc[r][g * 4 + 3]);
            }
        }
    }

    float k2r[16];
    int mr[16];
    #pragma unroll
    for (int g = 0; g < 4; ++g) {
        float4 kk = *reinterpret_cast<const float4*>(&k2s[g * 128 + l * 4]);
        k2r[g * 4 + 0] = kk.x; k2r[g * 4 + 1] = kk.y;
        k2r[g * 4 + 2] = kk.z; k2r[g * 4 + 3] = kk.w;
        #pragma unroll
        for (int e = 0; e < 4; ++e) mr[g * 4 + e] = ms[g * 128 + l * 4 + e];
    }

    for (int r = 0; r < 4; ++r) {
        const int t1 = t1Base + r0 + r;
        const float q2v = q2s[r0 + r];

        float lg[16];
        float mx = -3.4e38f;
        #pragma unroll
        for (int j = 0; j < 16; ++j) {
            lg[j] = -TEMP * (q2v + k2r[j] - 2.f * acc[r][j]);
            mx = fmaxf(mx, lg[j]);
        }
        #pragma unroll
        for (int o = 16; o > 0; o >>= 1)
            mx = fmaxf(mx, __shfl_xor_sync(0xffffffffu, mx, o));

        float wv[16];
        float sum = 0.f;
        #pragma unroll
        for (int j = 0; j < 16; ++j) {
            lg[j] -= mx;
            wv[j] = __expf(lg[j]);
            sum += wv[j];
        }
        #pragma unroll
        for (int o = 16; o > 0; o >>= 1)
            sum += __shfl_xor_sync(0xffffffffu, sum, o);
        const float lsum = __logf(sum);

        const float* pr = prior + ((size_t)b * TT1 + t1) * TT2;
        float* olp = outLP + ((size_t)b * TT1 + t1) * TT2;
        #pragma unroll
        for (int g = 0; g < 4; ++g) {
            float4 p4 = *reinterpret_cast<const float4*>(&pr[g * 128 + l * 4]);
            float pa[4] = {p4.x + 1e-8f, p4.y + 1e-8f, p4.z + 1e-8f, p4.w + 1e-8f};
            float4 o;
            o.x = lg[g * 4 + 0] - lsum + __logf(pa[0]);
            o.y = lg[g * 4 + 1] - lsum + __logf(pa[1]);
            o.z = lg[g * 4 + 2] - lsum + __logf(pa[2]);
            o.w = lg[g * 4 + 3] - lsum + __logf(pa[3]);
            *reinterpret_cast<float4*>(&olp[g * 128 + l * 4]) = o;
            #pragma unroll
            for (int e = 0; e < 4; ++e) {
                int j = g * 4 + e;
                wv[j] = mr[j] ? 0.f : wv[j] * pa[e];
            }
        }

        float s2 = 0.f;
        #pragma unroll
        for (int j = 0; j < 16; ++j) s2 += wv[j];
        #pragma unroll
        for (int o = 16; o > 0; o >>= 1)
            s2 += __shfl_xor_sync(0xffffffffu, s2, o);
        const float inv = 1.f / s2;

        float* oa = outA + ((size_t)b * TT1 + t1) * TT2;
        #pragma unroll
        for (int g = 0; g < 4; ++g) {
            float4 o;
            o.x = wv[g * 4 + 0] * inv; o.y = wv[g * 4 + 1] * inv;
            o.z = wv[g * 4 + 2] * inv; o.w = wv[g * 4 + 3] * inv;
            *reinterpret_cast<float4*>(&oa[g * 128 + l * 4]) = o;
        }
    }
}

// ---------------- launch ----------------------------------------------------
extern "C" void kernel_launch(void* const* d_in, const int* in_sizes, int n_in,
                              void* d_out, int out_size) {
    const float* queries = (const float*)d_in[0];
    const float* keys    = (const float*)d_in[1];
    const int*   mask    = (const int*)d_in[2];
    const float* prior   = (const float*)d_in[3];
    const float* spk     = (const float*)d_in[4];
    const float* kw1 = (const float*)d_in[5];
    const float* kb1 = (const float*)d_in[6];
    const float* kw2 = (const float*)d_in[7];
    const float* kb2 = (const float*)d_in[8];
    const float* qw1 = (const float*)d_in[9];
    const float* qb1 = (const float*)d_in[10];
    const float* qw2 = (const float*)d_in[11];
    const float* qb2 = (const float*)d_in[12];
    const float* qw3 = (const float*)d_in[13];
    const float* qb3 = (const float*)d_in[14];
    const float* kspk_w = (const float*)d_in[15];
    const float* kspk_b = (const float*)d_in[16];
    const float* qspk_w = (const float*)d_in[17];
    const float* qspk_b = (const float*)d_in[18];

    float* outA  = (float*)d_out;
    float* outLP = (float*)d_out + (size_t)BB * TT1 * TT2;

    float *kspk, *qspk, *kmid, *kenc, *qmid1, *qmid2, *qenc, *k2, *q2;
    cudaGetSymbolAddress((void**)&kspk,  g_kspk);
    cudaGetSymbolAddress((void**)&qspk,  g_qspk);
    cudaGetSymbolAddress((void**)&kmid,  g_kmid);
    cudaGetSymbolAddress((void**)&kenc,  g_kenc);
    cudaGetSymbolAddress((void**)&qmid1, g_qmid1);
    cudaGetSymbolAddress((void**)&qmid2, g_qmid2);
    cudaGetSymbolAddress((void**)&qenc,  g_qenc);
    cudaGetSymbolAddress((void**)&k2,    g_k2);
    cudaGetSymbolAddress((void**)&q2,    g_q2);

    // dynamic smem attributes (set every call; deterministic, capture-safe)
    cudaFuncSetAttribute(mma_convgemm3<3, true>,
                         cudaFuncAttributeMaxDynamicSharedMemorySize, CONV_SMEM_BYTES);
    cudaFuncSetAttribute(mma_convgemm3<1, true>,
                         cudaFuncAttributeMaxDynamicSharedMemorySize, CONV_SMEM_BYTES);
    cudaFuncSetAttribute(mma_convgemm3<1, false>,
                         cudaFuncAttributeMaxDynamicSharedMemorySize, CONV_SMEM_BYTES);
    size_t smem = (size_t)(NATT * TT2 + NATT * 32 + TT2 + 32) * sizeof(float)
                + TT2 * sizeof(int);
    cudaFuncSetAttribute(attn_kernel, cudaFuncAttributeMaxDynamicSharedMemorySize,
                         (int)smem);

    // 1. speaker projections
    spkproj_kernel<<<dim3(NTEXT, BB), 32>>>(spk, kspk_w, kspk_b, kspk, NTEXT);
    spkproj_kernel<<<dim3(NMEL, BB), 32>>>(spk, qspk_w, qspk_b, qspk, NMEL);

    // 2. keys conv1 (512->1024, k3) + relu
    mma_convgemm3<3, true><<<dim3(TT2 / CBN, 8, BB), 256, CONV_SMEM_BYTES>>>(
        kw1, kb1, keys, kspk, kmid, 1024, NTEXT, TT2);

    // 3. keys conv2 (1024->80, k1)
    mma_convgemm3<1, false><<<dim3(TT2 / CBN, 1, BB), 256, CONV_SMEM_BYTES>>>(
        kw2, kb2, kmid, nullptr, kenc, NATT, 1024, TT2);

    // 4. queries conv1 (80->160, k3) + relu
    mma_convgemm3<3, true><<<dim3(TT1 / CBN, 2, BB), 256, CONV_SMEM_BYTES>>>(
        qw1, qb1, queries, qspk, qmid1, 160, NMEL, TT1);

    // 5. queries conv2 (160->80, k1) + relu
    mma_convgemm3<1, true><<<dim3(TT1 / CBN, 1, BB), 256, CONV_SMEM_BYTES>>>(
        qw2, qb2, qmid1, nullptr, qmid2, NMEL, 160, TT1);

    // 6. queries conv3 (80->80, k1)
    mma_convgemm3<1, false><<<dim3(TT1 / CBN, 1, BB), 256, CONV_SMEM_BYTES>>>(
        qw3, qb3, qmid2, nullptr, qenc, NATT, NMEL, TT1);

    // 7. squared norms
    sumsq_kernel<<<dim3(TT2 / 256, BB), 256>>>(kenc, k2, NATT, TT2);
    sumsq_kernel<<<dim3(TT1 / 256, BB), 256>>>(qenc, q2, NATT, TT1);

    // 8. fused attention tail
    attn_kernel<<<dim3(TT1 / 32, BB), 256, smem>>>(
        qenc, kenc, q2, k2, prior, mask, outA, outLP);
}